// round 8
// baseline (speedup 1.0000x reference)
#include <cuda_runtime.h>

#define N_SPARSE 16
#define N_VARLEN 4
#define SEQ_L 50
#define VOCAB 1000000
#define EPSV 1e-8f
#define ROW_LEN (N_SPARSE + N_VARLEN * SEQ_L)   // 216
#define OUT_LEN (N_SPARSE + N_VARLEN)           // 20
#define WARPS_PER_BLOCK 8
#define THREADS (WARPS_PER_BLOCK * 32)          // 256
#define TAIL (SEQ_L - 32)                        // 18

__global__ __launch_bounds__(THREADS) void emb_pool_kernel(
    const int* __restrict__ X,
    const float* __restrict__ sparse_tables,
    const float* __restrict__ varlen_tables,
    float* __restrict__ out)
{
    const int w    = threadIdx.x >> 5;
    const int lane = threadIdx.x & 31;
    const int row  = blockIdx.x * WARPS_PER_BLOCK + w;

    const int* __restrict__ xr = X + (size_t)row * ROW_LEN;
    const bool tail_on = (lane < TAIL);

    // ---- Phase 1: all id loads (coalesced; default policy so X stays in L2) ----
    int sid = (lane < N_SPARSE) ? xr[lane] : 0;
    int ida[N_VARLEN], idb[N_VARLEN];
    #pragma unroll
    for (int v = 0; v < N_VARLEN; v++) {
        const int* ids = xr + N_SPARSE + v * SEQ_L;
        ida[v] = ids[lane];
        // Unconditional, in-bounds load; inactive lanes forced to id 0
        int ib = ids[32 + (tail_on ? lane : 0)];
        idb[v] = tail_on ? ib : 0;
    }

    // ---- Phase 2: all gathers unconditional, back-to-back (no @P guards) ----
    float sparse_val = 0.f;
    if (lane < N_SPARSE)
        sparse_val = __ldg(sparse_tables + (size_t)lane * VOCAB + sid);

    float ga[N_VARLEN], gb[N_VARLEN];
    #pragma unroll
    for (int v = 0; v < N_VARLEN; v++) {
        ga[v] = __ldg(varlen_tables + (size_t)v * VOCAB + ida[v]);
        gb[v] = __ldg(varlen_tables + (size_t)v * VOCAB + idb[v]);
    }

    // ---- Phase 3: masks + counts via ballot ----
    int cnt[N_VARLEN];
    float s[N_VARLEN];
    #pragma unroll
    for (int v = 0; v < N_VARLEN; v++) {
        bool p0 = (ida[v] != 0);
        bool p1 = (idb[v] != 0);              // inactive lanes have idb==0
        unsigned b0 = __ballot_sync(0xffffffffu, p0);
        unsigned b1 = __ballot_sync(0xffffffffu, p1);
        cnt[v] = __popc(b0) + __popc(b1);
        s[v] = (p0 ? ga[v] : 0.f) + (p1 ? gb[v] : 0.f);
    }

    // ---- Phase 4: sum reductions (4 independent shfl trees) ----
    #pragma unroll
    for (int o = 16; o; o >>= 1) {
        #pragma unroll
        for (int v = 0; v < N_VARLEN; v++)
            s[v] += __shfl_xor_sync(0xffffffffu, s[v], o);
    }

    // ---- Phase 5: single coalesced store, lanes 0..19 ----
    float val;
    if (lane < N_SPARSE) {
        val = sparse_val;
    } else {
        float sv, cv;
        if      (lane == 16) { sv = s[0]; cv = (float)cnt[0]; }
        else if (lane == 17) { sv = s[1]; cv = (float)cnt[1]; }
        else if (lane == 18) { sv = s[2]; cv = (float)cnt[2]; }
        else                 { sv = s[3]; cv = (float)cnt[3]; }
        val = __fdividef(sv, cv + EPSV);
    }
    if (lane < OUT_LEN)
        __stcs(out + (size_t)row * OUT_LEN + lane, val);
}

extern "C" void kernel_launch(void* const* d_in, const int* in_sizes, int n_in,
                              void* d_out, int out_size)
{
    const int*   X  = (const int*)d_in[0];
    const float* st = (const float*)d_in[1];
    const float* vt = (const float*)d_in[2];
    float* out = (float*)d_out;

    const int B = in_sizes[0] / ROW_LEN;       // 16384
    const int grid = B / WARPS_PER_BLOCK;      // 2048

    emb_pool_kernel<<<grid, THREADS>>>(X, st, vt, out);
}

// round 9
// speedup vs baseline: 1.0169x; 1.0169x over previous
#include <cuda_runtime.h>

#define N_SPARSE 16
#define N_VARLEN 4
#define SEQ_L 50
#define VOCAB 1000000
#define EPSV 1e-8f
#define ROW_LEN (N_SPARSE + N_VARLEN * SEQ_L)   // 216
#define OUT_LEN (N_SPARSE + N_VARLEN)           // 20
#define WARPS_PER_BLOCK 8
#define THREADS (WARPS_PER_BLOCK * 32)          // 256
#define TAIL (SEQ_L - 32)                        // 18
#define GRID 1024                                // <=1184 resident -> ONE wave
#define ROWS_PER_WARP 2                          // 1024*8*2 = 16384 exactly

__global__ __launch_bounds__(THREADS) void emb_pool_kernel(
    const int* __restrict__ X,
    const float* __restrict__ sparse_tables,
    const float* __restrict__ varlen_tables,
    float* __restrict__ out)
{
    const int lane = threadIdx.x & 31;
    const int wg   = blockIdx.x * WARPS_PER_BLOCK + (threadIdx.x >> 5);
    const bool tail_on = (lane < TAIL);

    #pragma unroll 1
    for (int r = 0; r < ROWS_PER_WARP; r++) {
        const int row = wg * ROWS_PER_WARP + r;
        const int* __restrict__ xr = X + (size_t)row * ROW_LEN;

        // ---- Phase 1: all id loads (coalesced, independent) ----
        int sid = (lane < N_SPARSE) ? xr[lane] : 0;
        int ida[N_VARLEN], idb[N_VARLEN];
        #pragma unroll
        for (int v = 0; v < N_VARLEN; v++) {
            const int* ids = xr + N_SPARSE + v * SEQ_L;
            ida[v] = ids[lane];
            idb[v] = tail_on ? ids[32 + lane] : 0;
        }

        // ---- Phase 2: all gathers back-to-back (L1-bypass, L2-cached) ----
        float sparse_val = 0.f;
        if (lane < N_SPARSE)
            sparse_val = __ldcg(sparse_tables + (size_t)lane * VOCAB + sid);

        float ga[N_VARLEN], gb[N_VARLEN];
        #pragma unroll
        for (int v = 0; v < N_VARLEN; v++) {
            ga[v] = (ida[v] != 0)
                  ? __ldcg(varlen_tables + (size_t)v * VOCAB + ida[v]) : 0.f;
            gb[v] = (idb[v] != 0)
                  ? __ldcg(varlen_tables + (size_t)v * VOCAB + idb[v]) : 0.f;
        }

        // ---- Phase 3: counts via ballot ----
        int cnt[N_VARLEN];
        #pragma unroll
        for (int v = 0; v < N_VARLEN; v++) {
            unsigned b0 = __ballot_sync(0xffffffffu, ida[v] != 0);
            unsigned b1 = __ballot_sync(0xffffffffu, idb[v] != 0);
            cnt[v] = __popc(b0) + __popc(b1);
        }

        // ---- Phase 4: sum reductions (4 independent shfl trees) ----
        float s[N_VARLEN];
        #pragma unroll
        for (int v = 0; v < N_VARLEN; v++)
            s[v] = ga[v] + gb[v];
        #pragma unroll
        for (int o = 16; o; o >>= 1) {
            #pragma unroll
            for (int v = 0; v < N_VARLEN; v++)
                s[v] += __shfl_xor_sync(0xffffffffu, s[v], o);
        }

        // ---- Phase 5: single coalesced store, lanes 0..19 ----
        float val;
        if (lane < N_SPARSE) {
            val = sparse_val;
        } else {
            float sv, cv;
            if      (lane == 16) { sv = s[0]; cv = (float)cnt[0]; }
            else if (lane == 17) { sv = s[1]; cv = (float)cnt[1]; }
            else if (lane == 18) { sv = s[2]; cv = (float)cnt[2]; }
            else                 { sv = s[3]; cv = (float)cnt[3]; }
            val = __fdividef(sv, cv + EPSV);
        }
        if (lane < OUT_LEN)
            __stcs(out + (size_t)row * OUT_LEN + lane, val);
    }
}

extern "C" void kernel_launch(void* const* d_in, const int* in_sizes, int n_in,
                              void* d_out, int out_size)
{
    const int*   X  = (const int*)d_in[0];
    const float* st = (const float*)d_in[1];
    const float* vt = (const float*)d_in[2];
    float* out = (float*)d_out;

    emb_pool_kernel<<<GRID, THREADS>>>(X, st, vt, out);
}